// round 8
// baseline (speedup 1.0000x reference)
#include <cuda_runtime.h>

#define CB 32
#define CT 1024
#define CS 256
#define CN 80

#define NEGF (-3.4028234663852886e38f)   // jnp.finfo(float32).min == -FLT_MAX
#define LOG2PI_F 1.8378770664093453f

// Scratch (global __device__ arrays are the allowed scratch mechanism)
static __device__ float g_ll[(size_t)CB * CT * CS];   // 33.5 MB masked log-likelihood
static __device__ int   g_idx[CB * CT];               // backtracked argmax index per (b,t)

// ---------------------------------------------------------------------------
// Kernel A: ll[b,t,s] = -0.5*(log(2pi) + |lat|^2 - 2*lat.mean + |mean|^2) * mask
// Tile 64t x 128s per block. NEW in R8: s-contiguous per-thread mapping
// (thread owns s = tx*8..tx*8+7, t = ty*4..ty*4+3) so all smem operand loads
// are LDS.128 (3 per n-iter instead of 12 scalar) and stores are STG.128.
// Unpadded rows (128/64 floats) -> 60.8KB smem -> 3 blocks/SM (24 warps).
// Per-element FP arithmetic chain identical to the rel_err=0.0 R7 version.
// ---------------------------------------------------------------------------
__global__ __launch_bounds__(256, 3)
void kernelA(const float* __restrict__ latent, const float* __restrict__ mean,
             const int* __restrict__ textlen, const int* __restrict__ mellen)
{
    extern __shared__ float sh[];
    float* smean  = sh;                          // [CN][128]  (s-half, n-major)
    float* slat   = smean + CN * 128;            // [CN][64]   (t-tile, n-major)
    float* smean2 = slat + CN * 64;              // [128]
    float* slat2  = smean2 + 128;                // [64]

    const int b   = blockIdx.x >> 5;
    const int rem = blockIdx.x & 31;
    const int tc  = rem >> 1;
    const int sc  = rem & 1;
    const int tid = threadIdx.x;
    const int tbase = tc * 64;
    const int sbase = sc * 128;

    // Load mean half-tile transposed (coalesced global reads)
    for (int idx = tid; idx < 128 * CN; idx += 256) {
        int sl = idx / CN, n = idx - sl * CN;
        smean[n * 128 + sl] = mean[((size_t)(b * CS + sbase + sl)) * CN + n];
    }
    // Load latent tile transposed
    for (int idx = tid; idx < 64 * CN; idx += 256) {
        int tl = idx / CN, n = idx - tl * CN;
        slat[n * 64 + tl] = latent[((size_t)(b * CT + tbase + tl)) * CN + n];
    }
    __syncthreads();

    // Row norms (same sequential-n order as before: bit-exact)
    if (tid < 128) {
        float acc = 0.f;
        #pragma unroll 4
        for (int n = 0; n < CN; n++) {
            float v = smean[n * 128 + tid];
            acc = __fadd_rn(acc, __fmul_rn(v, v));
        }
        smean2[tid] = acc;
    } else if (tid < 192) {
        int tl = tid - 128;
        float acc = 0.f;
        #pragma unroll 4
        for (int n = 0; n < CN; n++) {
            float v = slat[n * 64 + tl];
            acc = __fadd_rn(acc, __fmul_rn(v, v));
        }
        slat2[tl] = acc;
    }
    __syncthreads();

    const int tx = tid & 15;    // s group: s_local = tx*8 + i (i<8, contiguous)
    const int ty = tid >> 4;    // t group: t_local = ty*4 + j (j<4, contiguous)

    float acc[4][8];
    #pragma unroll
    for (int j = 0; j < 4; j++)
        #pragma unroll
        for (int i = 0; i < 8; i++) acc[j][i] = 0.f;

    const float* mrow = smean + tx * 8;
    const float* arow = slat + ty * 4;

    #pragma unroll 2
    for (int n = 0; n < CN; n++) {
        float4 av = *(const float4*)(arow + n * 64);
        float4 m0 = *(const float4*)(mrow + n * 128);
        float4 m1 = *(const float4*)(mrow + n * 128 + 4);
        float a[4] = {av.x, av.y, av.z, av.w};
        float m[8] = {m0.x, m0.y, m0.z, m0.w, m1.x, m1.y, m1.z, m1.w};
        #pragma unroll
        for (int j = 0; j < 4; j++)
            #pragma unroll
            for (int i = 0; i < 8; i++)
                acc[j][i] = __fmaf_rn(a[j], m[i], acc[j][i]);
    }

    const int tl_b = textlen[b];
    const int ml_b = mellen[b];
    const float4 mn2a = *(const float4*)(smean2 + tx * 8);
    const float4 mn2b = *(const float4*)(smean2 + tx * 8 + 4);
    const float mn2[8] = {mn2a.x, mn2a.y, mn2a.z, mn2a.w,
                          mn2b.x, mn2b.y, mn2b.z, mn2b.w};

    #pragma unroll
    for (int j = 0; j < 4; j++) {
        int tl = ty * 4 + j;
        int tg = tbase + tl;
        float l2 = slat2[tl];
        float rowmask = (tg < ml_b) ? 1.f : 0.f;
        float* outrow = g_ll + ((size_t)(b * CT + tg)) * CS + sbase + tx * 8;
        float ll[8];
        #pragma unroll
        for (int i = 0; i < 8; i++) {
            // identical op chain to R7: fma(-2,acc,l2) + mean2; *mask
            float dist = __fadd_rn(__fmaf_rn(-2.f, acc[j][i], l2), mn2[i]);
            float msk  = (sbase + tx * 8 + i < tl_b) ? rowmask : 0.f;
            ll[i] = __fmul_rn(__fmul_rn(-0.5f, __fadd_rn(LOG2PI_F, dist)), msk);
        }
        ((float4*)outrow)[0] = make_float4(ll[0], ll[1], ll[2], ll[3]);
        ((float4*)outrow)[1] = make_float4(ll[4], ll[5], ll[6], ll[7]);
    }
}

// ---------------------------------------------------------------------------
// Kernel B: Viterbi forward + backtrack. ONE warp per batch. Unchanged from
// the passing R7 version (rel_err 0.0, ring buffers in registers).
// ---------------------------------------------------------------------------
__global__ __launch_bounds__(32, 1)
void kernelB(const int* __restrict__ textlen, const int* __restrict__ mellen)
{
    __shared__ unsigned char sdir[CT * 32];   // [t*32 + (s>>3)], bit (s&7); 1 = stay

    const int b = blockIdx.x;
    const int L = threadIdx.x;
    const int tl_b = textlen[b];
    const int ml_b = mellen[b];

    const float4* __restrict__ base = (const float4*)(g_ll + (size_t)b * CT * CS);
    const int roff = L * 2;   // float4 index: lane L covers s = 8L..8L+7

    float p[8];
    #pragma unroll
    for (int k = 0; k < 8; k++) p[k] = 0.f;

    // 8-deep register ring (ring slot == unroll position -> compile-time index)
    float4 bufA[8], bufB[8];
    #pragma unroll
    for (int r = 0; r < 8; r++) {
        bufA[r] = base[r * (CS / 4) + roff];
        bufB[r] = base[r * (CS / 4) + roff + 1];
    }

#define BSTEP(T, U, MASKED)                                                   \
    {                                                                         \
        const int t_ = (T);                                                   \
        float4 lo = bufA[U], hi = bufB[U];                                    \
        int tp_ = t_ + 8;                                                     \
        if (tp_ < CT) {                                                       \
            bufA[U] = base[tp_ * (CS / 4) + roff];                            \
            bufB[U] = base[tp_ * (CS / 4) + roff + 1];                        \
        }                                                                     \
        float llv[8] = {lo.x, lo.y, lo.z, lo.w, hi.x, hi.y, hi.z, hi.w};      \
        float prevv = __shfl_up_sync(0xffffffffu, p[7], 1);                   \
        if (L == 0) prevv = NEGF;                                             \
        unsigned bits = 0;                                                    \
        _Pragma("unroll")                                                     \
        for (int k = 0; k < 8; k++) {                                         \
            float cur = p[k];                                                 \
            bits |= (cur >= prevv ? 1u : 0u) << k;                            \
            float m  = fmaxf(cur, prevv);                                     \
            float nn = __fadd_rn(m, llv[k]);                                  \
            p[k] = MASKED ? ((((L << 3) + k) <= t_) ? nn : NEGF) : nn;        \
            prevv = cur;                                                      \
        }                                                                     \
        sdir[t_ * 32 + L] = (unsigned char)bits;                              \
    }

    for (int t0 = 0; t0 < 256; t0 += 8) {
        BSTEP(t0 + 0, 0, true) BSTEP(t0 + 1, 1, true)
        BSTEP(t0 + 2, 2, true) BSTEP(t0 + 3, 3, true)
        BSTEP(t0 + 4, 4, true) BSTEP(t0 + 5, 5, true)
        BSTEP(t0 + 6, 6, true) BSTEP(t0 + 7, 7, true)
    }
    for (int t0 = 256; t0 < CT; t0 += 8) {
        BSTEP(t0 + 0, 0, false) BSTEP(t0 + 1, 1, false)
        BSTEP(t0 + 2, 2, false) BSTEP(t0 + 3, 3, false)
        BSTEP(t0 + 4, 4, false) BSTEP(t0 + 5, 5, false)
        BSTEP(t0 + 6, 6, false) BSTEP(t0 + 7, 7, false)
    }
#undef BSTEP

    __syncwarp();

    // Backtrack. Reference forces dir=1 wherever attnmask==0, so for
    // t >= mellen the index stays pinned at textlen-1; inside the mask the
    // traced path never enters s >= textlen, so raw mk bits are correct.
    // De-chained in groups of 4 rows: index span <= 4 => 2 candidate bytes.
    if (L == 0) {
        int* gout = g_idx + b * CT;
        int idx = tl_b - 1;
        int t = CT - 1;
        for (; t >= ml_b; --t) gout[t] = idx;
        while (t >= 3) {
            int A  = idx >> 3;
            int Bq = ((idx >= 3) ? (idx - 3) : 0) >> 3;
            unsigned hi0 = sdir[t * 32 + A],       lo0 = sdir[t * 32 + Bq];
            unsigned hi1 = sdir[(t - 1) * 32 + A], lo1 = sdir[(t - 1) * 32 + Bq];
            unsigned hi2 = sdir[(t - 2) * 32 + A], lo2 = sdir[(t - 2) * 32 + Bq];
            unsigned hi3 = sdir[(t - 3) * 32 + A], lo3 = sdir[(t - 3) * 32 + Bq];
            (void)lo0;
            gout[t] = idx;
            idx += (int)((hi0 >> (idx & 7)) & 1u) - 1;
            gout[t - 1] = idx;
            unsigned wd = ((idx >> 3) == A) ? hi1 : lo1;
            idx += (int)((wd >> (idx & 7)) & 1u) - 1;
            gout[t - 2] = idx;
            wd = ((idx >> 3) == A) ? hi2 : lo2;
            idx += (int)((wd >> (idx & 7)) & 1u) - 1;
            gout[t - 3] = idx;
            wd = ((idx >> 3) == A) ? hi3 : lo3;
            idx += (int)((wd >> (idx & 7)) & 1u) - 1;
            t -= 4;
        }
        for (; t >= 0; --t) {
            gout[t] = idx;
            idx += (int)((sdir[t * 32 + (idx >> 3)] >> (idx & 7)) & 1u) - 1;
        }
    }
}

// ---------------------------------------------------------------------------
// Kernel C: write residual [B,T,N] then attn [B,T,S] into d_out (float4).
// Unchanged from the passing R7 version.
// ---------------------------------------------------------------------------
__global__ __launch_bounds__(256)
void kernelC(const float* __restrict__ latent, const float* __restrict__ mean,
             const int* __restrict__ mellen, float* __restrict__ out)
{
    const int RES4 = CB * CT * CN / 4;           // 655360
    const int TOT4 = RES4 + CB * CT * CS / 4;    // 2752512
    int i = blockIdx.x * blockDim.x + threadIdx.x;
    if (i >= TOT4) return;
    float4* out4 = (float4*)out;

    if (i < RES4) {
        int f  = i << 2;
        int bt = f / CN;
        int n  = f - bt * CN;
        int b  = bt >> 10;
        int t  = bt & (CT - 1);
        float4 r = ((const float4*)latent)[i];
        if (t < __ldg(&mellen[b])) {
            int sidx = g_idx[bt];
            float4 mv = *(const float4*)(mean + ((size_t)(b * CS + sidx)) * CN + n);
            r.x -= mv.x; r.y -= mv.y; r.z -= mv.z; r.w -= mv.w;
        }
        out4[i] = r;
    } else {
        int f  = (i - RES4) << 2;
        int bt = f >> 8;                 // / CS
        int s0 = f & (CS - 1);
        int b  = bt >> 10;
        int t  = bt & (CT - 1);
        float4 v = make_float4(0.f, 0.f, 0.f, 0.f);
        if (t < __ldg(&mellen[b])) {
            int sidx = g_idx[bt];        // always < textlen[b] => textmask == 1
            v.x = (sidx == s0)     ? 1.f : 0.f;
            v.y = (sidx == s0 + 1) ? 1.f : 0.f;
            v.z = (sidx == s0 + 2) ? 1.f : 0.f;
            v.w = (sidx == s0 + 3) ? 1.f : 0.f;
        }
        out4[i] = v;
    }
}

extern "C" void kernel_launch(void* const* d_in, const int* in_sizes, int n_in,
                              void* d_out, int out_size)
{
    const float* latent  = (const float*)d_in[0];   // [32,1024,80]
    const float* mean    = (const float*)d_in[1];   // [32,256,80]
    const int*   textlen = (const int*)d_in[2];     // [32]
    const int*   mellen  = (const int*)d_in[3];     // [32]
    float* out = (float*)d_out;                     // residual (B*T*N) ++ attn (B*T*S)

    const size_t shA = (size_t)(CN * 128 + CN * 64 + 128 + 64) * sizeof(float);
    cudaFuncSetAttribute(kernelA, cudaFuncAttributeMaxDynamicSharedMemorySize, (int)shA);

    kernelA<<<CB * 32, 256, shA>>>(latent, mean, textlen, mellen);
    kernelB<<<CB, 32>>>(textlen, mellen);

    const int TOT4 = (CB * CT * CN + CB * CT * CS) / 4;
    kernelC<<<(TOT4 + 255) / 256, 256>>>(latent, mean, mellen, out);
}

// round 9
// speedup vs baseline: 1.3889x; 1.3889x over previous
#include <cuda_runtime.h>

#define CB 32
#define CT 1024
#define CS 256
#define CN 80

#define NEGF (-3.4028234663852886e38f)   // jnp.finfo(float32).min == -FLT_MAX
#define LOG2PI_F 1.8378770664093453f

// Scratch (global __device__ arrays are the allowed scratch mechanism)
static __device__ float g_ll[(size_t)CB * CT * CS];   // 33.5 MB masked log-likelihood
static __device__ int   g_idx[CB * CT];               // backtracked argmax index per (b,t)

// ---------------------------------------------------------------------------
// Kernel A: ll[b,t,s] = -0.5*(log(2pi) + |lat|^2 - 2*lat.mean + |mean|^2) * mask
// EXACT R7 body (interleaved s-mapping: broadcast-friendly, conflict-free LDS
// — the R8 float4 mapping caused 4-way bank conflicts, L1 84%) plus an early
// exit for fully-masked t-chunks (tbase >= mellen[b]): those ll rows are
// never consumed by kernel B (forward stops at mellen; backtrack pins there).
// ---------------------------------------------------------------------------
__global__ __launch_bounds__(256, 2)
void kernelA(const float* __restrict__ latent, const float* __restrict__ mean,
             const int* __restrict__ textlen, const int* __restrict__ mellen)
{
    extern __shared__ float sh[];
    float* smean  = sh;                          // [CN][129]  (s-half: 128 + pad)
    float* slat   = smean + CN * 129;            // [CN][65]   (t-tile: 64 + pad)
    float* smean2 = slat + CN * 65;              // [128]
    float* slat2  = smean2 + 128;                // [64]

    const int b   = blockIdx.x >> 5;
    const int rem = blockIdx.x & 31;
    const int tc  = rem >> 1;
    const int sc  = rem & 1;
    const int tid = threadIdx.x;
    const int tbase = tc * 64;
    const int sbase = sc * 128;

    const int ml_b = mellen[b];
    if (tbase >= ml_b) return;    // fully-masked chunk: rows never consumed
    const int tl_b = textlen[b];

    for (int idx = tid; idx < 128 * CN; idx += 256) {
        int sl = idx / CN, n = idx - sl * CN;
        smean[n * 129 + sl] = mean[((size_t)(b * CS + sbase + sl)) * CN + n];
    }
    for (int idx = tid; idx < 64 * CN; idx += 256) {
        int tl = idx / CN, n = idx - tl * CN;
        slat[n * 65 + tl] = latent[((size_t)(b * CT + tbase + tl)) * CN + n];
    }
    __syncthreads();

    if (tid < 128) {
        float acc = 0.f;
        #pragma unroll 4
        for (int n = 0; n < CN; n++) {
            float v = smean[n * 129 + tid];
            acc = __fadd_rn(acc, __fmul_rn(v, v));
        }
        smean2[tid] = acc;
    } else if (tid < 192) {
        int tl = tid - 128;
        float acc = 0.f;
        #pragma unroll 4
        for (int n = 0; n < CN; n++) {
            float v = slat[n * 65 + tl];
            acc = __fadd_rn(acc, __fmul_rn(v, v));
        }
        slat2[tl] = acc;
    }
    __syncthreads();

    const int tx = tid & 15;    // s lane: s_local = tx + 16*i (i<8)
    const int ty = tid >> 4;    // t group: t_local = ty*4 + j (j<4)

    float acc[4][8];
    #pragma unroll
    for (int j = 0; j < 4; j++)
        #pragma unroll
        for (int i = 0; i < 8; i++) acc[j][i] = 0.f;

    const float* mrow = smean + tx;
    const float* arow = slat + ty * 4;

    #pragma unroll 2
    for (int n = 0; n < CN; n++) {
        float a[4], m[8];
        #pragma unroll
        for (int j = 0; j < 4; j++) a[j] = arow[n * 65 + j];
        #pragma unroll
        for (int i = 0; i < 8; i++) m[i] = mrow[n * 129 + 16 * i];
        #pragma unroll
        for (int j = 0; j < 4; j++)
            #pragma unroll
            for (int i = 0; i < 8; i++)
                acc[j][i] = __fmaf_rn(a[j], m[i], acc[j][i]);
    }

    #pragma unroll
    for (int j = 0; j < 4; j++) {
        int tl = ty * 4 + j;
        int tg = tbase + tl;
        float l2 = slat2[tl];
        float rowmask = (tg < ml_b) ? 1.f : 0.f;
        float* outrow = g_ll + ((size_t)(b * CT + tg)) * CS + sbase;
        #pragma unroll
        for (int i = 0; i < 8; i++) {
            int sl = tx + 16 * i;
            float dist = __fadd_rn(__fmaf_rn(-2.f, acc[j][i], l2), smean2[sl]);
            float msk  = (sbase + sl < tl_b) ? rowmask : 0.f;
            float ll   = __fmul_rn(__fmul_rn(-0.5f, __fadd_rn(LOG2PI_F, dist)), msk);
            outrow[sl] = ll;
        }
    }
}

// ---------------------------------------------------------------------------
// Kernel B: Viterbi forward + backtrack. ONE warp per batch; ring buffers in
// registers (R7, rel_err 0.0). NEW in R9: forward loop stops at mellen[b]
// (mellen >= 512 always, so the masked t<256 loop keeps its static bound).
// The <=7-step overrun past mellen reads zero rows (live A-block wrote them);
// its dir bits are never read — backtrack pins idx for t >= mellen.
// ---------------------------------------------------------------------------
__global__ __launch_bounds__(32, 1)
void kernelB(const int* __restrict__ textlen, const int* __restrict__ mellen)
{
    __shared__ unsigned char sdir[CT * 32];   // [t*32 + (s>>3)], bit (s&7); 1 = stay

    const int b = blockIdx.x;
    const int L = threadIdx.x;
    const int tl_b = textlen[b];
    const int ml_b = mellen[b];

    const float4* __restrict__ base = (const float4*)(g_ll + (size_t)b * CT * CS);
    const int roff = L * 2;   // float4 index: lane L covers s = 8L..8L+7

    float p[8];
    #pragma unroll
    for (int k = 0; k < 8; k++) p[k] = 0.f;

    // 8-deep register ring (ring slot == unroll position -> compile-time index)
    float4 bufA[8], bufB[8];
    #pragma unroll
    for (int r = 0; r < 8; r++) {
        bufA[r] = base[r * (CS / 4) + roff];
        bufB[r] = base[r * (CS / 4) + roff + 1];
    }

#define BSTEP(T, U, MASKED)                                                   \
    {                                                                         \
        const int t_ = (T);                                                   \
        float4 lo = bufA[U], hi = bufB[U];                                    \
        int tp_ = t_ + 8;                                                     \
        if (tp_ < CT) {                                                       \
            bufA[U] = base[tp_ * (CS / 4) + roff];                            \
            bufB[U] = base[tp_ * (CS / 4) + roff + 1];                        \
        }                                                                     \
        float llv[8] = {lo.x, lo.y, lo.z, lo.w, hi.x, hi.y, hi.z, hi.w};      \
        float prevv = __shfl_up_sync(0xffffffffu, p[7], 1);                   \
        if (L == 0) prevv = NEGF;                                             \
        unsigned bits = 0;                                                    \
        _Pragma("unroll")                                                     \
        for (int k = 0; k < 8; k++) {                                         \
            float cur = p[k];                                                 \
            bits |= (cur >= prevv ? 1u : 0u) << k;                            \
            float m  = fmaxf(cur, prevv);                                     \
            float nn = __fadd_rn(m, llv[k]);                                  \
            p[k] = MASKED ? ((((L << 3) + k) <= t_) ? nn : NEGF) : nn;        \
            prevv = cur;                                                      \
        }                                                                     \
        sdir[t_ * 32 + L] = (unsigned char)bits;                              \
    }

    for (int t0 = 0; t0 < 256; t0 += 8) {
        BSTEP(t0 + 0, 0, true) BSTEP(t0 + 1, 1, true)
        BSTEP(t0 + 2, 2, true) BSTEP(t0 + 3, 3, true)
        BSTEP(t0 + 4, 4, true) BSTEP(t0 + 5, 5, true)
        BSTEP(t0 + 6, 6, true) BSTEP(t0 + 7, 7, true)
    }
    for (int t0 = 256; t0 < ml_b; t0 += 8) {     // stop at mellen: rows beyond
        BSTEP(t0 + 0, 0, false) BSTEP(t0 + 1, 1, false)  // are masked (dir=1,
        BSTEP(t0 + 2, 2, false) BSTEP(t0 + 3, 3, false)  // pinned in backtrack)
        BSTEP(t0 + 4, 4, false) BSTEP(t0 + 5, 5, false)
        BSTEP(t0 + 6, 6, false) BSTEP(t0 + 7, 7, false)
    }
#undef BSTEP

    __syncwarp();

    // Backtrack. Reference forces dir=1 wherever attnmask==0, so for
    // t >= mellen the index stays pinned at textlen-1; inside the mask the
    // traced path never enters s >= textlen, so raw mk bits are correct.
    // De-chained in groups of 4 rows: index span <= 4 => 2 candidate bytes.
    if (L == 0) {
        int* gout = g_idx + b * CT;
        int idx = tl_b - 1;
        int t = CT - 1;
        for (; t >= ml_b; --t) gout[t] = idx;
        while (t >= 3) {
            int A  = idx >> 3;
            int Bq = ((idx >= 3) ? (idx - 3) : 0) >> 3;
            unsigned hi0 = sdir[t * 32 + A],       lo0 = sdir[t * 32 + Bq];
            unsigned hi1 = sdir[(t - 1) * 32 + A], lo1 = sdir[(t - 1) * 32 + Bq];
            unsigned hi2 = sdir[(t - 2) * 32 + A], lo2 = sdir[(t - 2) * 32 + Bq];
            unsigned hi3 = sdir[(t - 3) * 32 + A], lo3 = sdir[(t - 3) * 32 + Bq];
            (void)lo0;
            gout[t] = idx;
            idx += (int)((hi0 >> (idx & 7)) & 1u) - 1;
            gout[t - 1] = idx;
            unsigned wd = ((idx >> 3) == A) ? hi1 : lo1;
            idx += (int)((wd >> (idx & 7)) & 1u) - 1;
            gout[t - 2] = idx;
            wd = ((idx >> 3) == A) ? hi2 : lo2;
            idx += (int)((wd >> (idx & 7)) & 1u) - 1;
            gout[t - 3] = idx;
            wd = ((idx >> 3) == A) ? hi3 : lo3;
            idx += (int)((wd >> (idx & 7)) & 1u) - 1;
            t -= 4;
        }
        for (; t >= 0; --t) {
            gout[t] = idx;
            idx += (int)((sdir[t * 32 + (idx >> 3)] >> (idx & 7)) & 1u) - 1;
        }
    }
}

// ---------------------------------------------------------------------------
// Kernel C: write residual [B,T,N] then attn [B,T,S] into d_out (float4).
// Unchanged from the passing R7 version.
// ---------------------------------------------------------------------------
__global__ __launch_bounds__(256)
void kernelC(const float* __restrict__ latent, const float* __restrict__ mean,
             const int* __restrict__ mellen, float* __restrict__ out)
{
    const int RES4 = CB * CT * CN / 4;           // 655360
    const int TOT4 = RES4 + CB * CT * CS / 4;    // 2752512
    int i = blockIdx.x * blockDim.x + threadIdx.x;
    if (i >= TOT4) return;
    float4* out4 = (float4*)out;

    if (i < RES4) {
        int f  = i << 2;
        int bt = f / CN;
        int n  = f - bt * CN;
        int b  = bt >> 10;
        int t  = bt & (CT - 1);
        float4 r = ((const float4*)latent)[i];
        if (t < __ldg(&mellen[b])) {
            int sidx = g_idx[bt];
            float4 mv = *(const float4*)(mean + ((size_t)(b * CS + sidx)) * CN + n);
            r.x -= mv.x; r.y -= mv.y; r.z -= mv.z; r.w -= mv.w;
        }
        out4[i] = r;
    } else {
        int f  = (i - RES4) << 2;
        int bt = f >> 8;                 // / CS
        int s0 = f & (CS - 1);
        int b  = bt >> 10;
        int t  = bt & (CT - 1);
        float4 v = make_float4(0.f, 0.f, 0.f, 0.f);
        if (t < __ldg(&mellen[b])) {
            int sidx = g_idx[bt];        // always < textlen[b] => textmask == 1
            v.x = (sidx == s0)     ? 1.f : 0.f;
            v.y = (sidx == s0 + 1) ? 1.f : 0.f;
            v.z = (sidx == s0 + 2) ? 1.f : 0.f;
            v.w = (sidx == s0 + 3) ? 1.f : 0.f;
        }
        out4[i] = v;
    }
}

extern "C" void kernel_launch(void* const* d_in, const int* in_sizes, int n_in,
                              void* d_out, int out_size)
{
    const float* latent  = (const float*)d_in[0];   // [32,1024,80]
    const float* mean    = (const float*)d_in[1];   // [32,256,80]
    const int*   textlen = (const int*)d_in[2];     // [32]
    const int*   mellen  = (const int*)d_in[3];     // [32]
    float* out = (float*)d_out;                     // residual (B*T*N) ++ attn (B*T*S)

    const size_t shA = (size_t)(CN * 129 + CN * 65 + 128 + 64) * sizeof(float);
    cudaFuncSetAttribute(kernelA, cudaFuncAttributeMaxDynamicSharedMemorySize, (int)shA);

    kernelA<<<CB * 32, 256, shA>>>(latent, mean, textlen, mellen);
    kernelB<<<CB, 32>>>(textlen, mellen);

    const int TOT4 = (CB * CT * CN + CB * CT * CS) / 4;
    kernelC<<<(TOT4 + 255) / 256, 256>>>(latent, mean, mellen, out);
}

// round 10
// speedup vs baseline: 1.4647x; 1.0546x over previous
#include <cuda_runtime.h>

#define CB 32
#define CT 1024
#define CS 256
#define CN 80

#define NEGF (-3.4028234663852886e38f)   // jnp.finfo(float32).min == -FLT_MAX
#define LOG2PI_F 1.8378770664093453f

// Scratch (global __device__ arrays are the allowed scratch mechanism)
static __device__ float g_ll[(size_t)CB * CT * CS];   // 33.5 MB masked log-likelihood
static __device__ int   g_idx[CB * CT];               // backtracked argmax index per (b,t)
static __device__ int   g_flag[CB * 16];              // per-(b,tc) chunk-ready counters
                                                      // (zero at load; kernelC re-zeroes)

// ---------------------------------------------------------------------------
// Fused kernel A+B.
//   blocks 0..31     : B role — Viterbi forward + backtrack, one warp/batch,
//                      consuming g_ll chunks as A produces them (flag spin).
//   blocks 32..1055  : A role — 64t x 128s ll tiles, chunk-major order
//                      (i = cc*32 + b) so every batch's chunk 0 lands in wave 1.
// Per-element arithmetic identical to the rel_err=0.0 R9 kernels.
// ---------------------------------------------------------------------------
__global__ __launch_bounds__(256, 2)
void kernelAB(const float* __restrict__ latent, const float* __restrict__ mean,
              const int* __restrict__ textlen, const int* __restrict__ mellen)
{
    extern __shared__ float sh[];

    if (blockIdx.x >= 32) {
        // ================= A role: ll producer =================
        float* smean  = sh;                          // [CN][129]
        float* slat   = smean + CN * 129;            // [CN][65]
        float* smean2 = slat + CN * 65;              // [128]
        float* slat2  = smean2 + 128;                // [64]

        const int i   = blockIdx.x - 32;
        const int b   = i & 31;
        const int cc  = i >> 5;          // chunk-major: all batches' chunk cc together
        const int tc  = cc >> 1;
        const int sc  = cc & 1;
        const int tid = threadIdx.x;
        const int tbase = tc * 64;
        const int sbase = sc * 128;

        const int ml_b = mellen[b];
        if (tbase >= ml_b) {             // fully-masked chunk: rows never consumed,
            if (tid == 0) atomicAdd(&g_flag[b * 16 + tc], 1);   // but must signal
            return;
        }
        const int tl_b = textlen[b];

        for (int idx = tid; idx < 128 * CN; idx += 256) {
            int sl = idx / CN, n = idx - sl * CN;
            smean[n * 129 + sl] = mean[((size_t)(b * CS + sbase + sl)) * CN + n];
        }
        for (int idx = tid; idx < 64 * CN; idx += 256) {
            int tl = idx / CN, n = idx - tl * CN;
            slat[n * 65 + tl] = latent[((size_t)(b * CT + tbase + tl)) * CN + n];
        }
        __syncthreads();

        if (tid < 128) {
            float acc = 0.f;
            #pragma unroll 4
            for (int n = 0; n < CN; n++) {
                float v = smean[n * 129 + tid];
                acc = __fadd_rn(acc, __fmul_rn(v, v));
            }
            smean2[tid] = acc;
        } else if (tid < 192) {
            int tl = tid - 128;
            float acc = 0.f;
            #pragma unroll 4
            for (int n = 0; n < CN; n++) {
                float v = slat[n * 65 + tl];
                acc = __fadd_rn(acc, __fmul_rn(v, v));
            }
            slat2[tl] = acc;
        }
        __syncthreads();

        const int tx = tid & 15;    // s lane: s_local = tx + 16*i2 (i2<8)
        const int ty = tid >> 4;    // t group: t_local = ty*4 + j (j<4)

        float acc[4][8];
        #pragma unroll
        for (int j = 0; j < 4; j++)
            #pragma unroll
            for (int i2 = 0; i2 < 8; i2++) acc[j][i2] = 0.f;

        const float* mrow = smean + tx;
        const float* arow = slat + ty * 4;

        #pragma unroll 2
        for (int n = 0; n < CN; n++) {
            float a[4], m[8];
            #pragma unroll
            for (int j = 0; j < 4; j++) a[j] = arow[n * 65 + j];
            #pragma unroll
            for (int i2 = 0; i2 < 8; i2++) m[i2] = mrow[n * 129 + 16 * i2];
            #pragma unroll
            for (int j = 0; j < 4; j++)
                #pragma unroll
                for (int i2 = 0; i2 < 8; i2++)
                    acc[j][i2] = __fmaf_rn(a[j], m[i2], acc[j][i2]);
        }

        #pragma unroll
        for (int j = 0; j < 4; j++) {
            int tl = ty * 4 + j;
            int tg = tbase + tl;
            float l2 = slat2[tl];
            float rowmask = (tg < ml_b) ? 1.f : 0.f;
            float* outrow = g_ll + ((size_t)(b * CT + tg)) * CS + sbase;
            #pragma unroll
            for (int i2 = 0; i2 < 8; i2++) {
                int sl = tx + 16 * i2;
                float dist = __fadd_rn(__fmaf_rn(-2.f, acc[j][i2], l2), smean2[sl]);
                float msk  = (sbase + sl < tl_b) ? rowmask : 0.f;
                float ll   = __fmul_rn(__fmul_rn(-0.5f, __fadd_rn(LOG2PI_F, dist)), msk);
                outrow[sl] = ll;
            }
        }

        // signal chunk ready (canonical: stores -> fence -> bar -> one atomic)
        __threadfence();
        __syncthreads();
        if (tid == 0) atomicAdd(&g_flag[b * 16 + tc], 1);
        return;
    }

    // ================= B role: Viterbi consumer =================
    if (threadIdx.x >= 32) return;       // one warp per batch
    unsigned char* sdir = (unsigned char*)sh;   // [CT*32]: dir bits, 1 = stay

    const int b = blockIdx.x;
    const int L = threadIdx.x;
    const int tl_b = textlen[b];
    const int ml_b = mellen[b];

    const float4* __restrict__ base = (const float4*)(g_ll + (size_t)b * CT * CS);
    const int roff = L * 2;   // float4 index: lane L covers s = 8L..8L+7

    const int* fl = g_flag + b * 16;
    int ready = 0;            // chunks confirmed ready (both s-halves)

#define WAITCH(CN_)                                                           \
    {                                                                         \
        int cw_ = (CN_);                                                      \
        if (ready <= cw_) {                                                   \
            while (ready <= cw_) {                                            \
                if (*(volatile int*)(fl + ready) >= 2) ready++;               \
            }                                                                 \
            __threadfence();                                                  \
        }                                                                     \
        asm volatile("" ::: "memory");                                        \
    }

    float p[8];
    #pragma unroll
    for (int k = 0; k < 8; k++) p[k] = 0.f;

    WAITCH(0)
    // 8-deep register ring (ring slot == unroll position -> compile-time index)
    float4 bufA[8], bufB[8];
    #pragma unroll
    for (int r = 0; r < 8; r++) {
        bufA[r] = base[r * (CS / 4) + roff];
        bufB[r] = base[r * (CS / 4) + roff + 1];
    }

#define BSTEP(T, U, MASKED)                                                   \
    {                                                                         \
        const int t_ = (T);                                                   \
        float4 lo = bufA[U], hi = bufB[U];                                    \
        int tp_ = t_ + 8;                                                     \
        if (tp_ < CT) {                                                       \
            bufA[U] = base[tp_ * (CS / 4) + roff];                            \
            bufB[U] = base[tp_ * (CS / 4) + roff + 1];                        \
        }                                                                     \
        float llv[8] = {lo.x, lo.y, lo.z, lo.w, hi.x, hi.y, hi.z, hi.w};      \
        float prevv = __shfl_up_sync(0xffffffffu, p[7], 1);                   \
        if (L == 0) prevv = NEGF;                                             \
        unsigned bits = 0;                                                    \
        _Pragma("unroll")                                                     \
        for (int k = 0; k < 8; k++) {                                         \
            float cur = p[k];                                                 \
            bits |= (cur >= prevv ? 1u : 0u) << k;                            \
            float m  = fmaxf(cur, prevv);                                     \
            float nn = __fadd_rn(m, llv[k]);                                  \
            p[k] = MASKED ? ((((L << 3) + k) <= t_) ? nn : NEGF) : nn;        \
            prevv = cur;                                                      \
        }                                                                     \
        sdir[t_ * 32 + L] = (unsigned char)bits;                              \
    }

    for (int t0 = 0; t0 < 256; t0 += 8) {
        int cn = (t0 + 15) >> 6;
        WAITCH(cn)
        BSTEP(t0 + 0, 0, true) BSTEP(t0 + 1, 1, true)
        BSTEP(t0 + 2, 2, true) BSTEP(t0 + 3, 3, true)
        BSTEP(t0 + 4, 4, true) BSTEP(t0 + 5, 5, true)
        BSTEP(t0 + 6, 6, true) BSTEP(t0 + 7, 7, true)
    }
    for (int t0 = 256; t0 < ml_b; t0 += 8) {     // rows >= mellen are masked
        int cn = (t0 + 15) >> 6; if (cn > 15) cn = 15;
        WAITCH(cn)
        BSTEP(t0 + 0, 0, false) BSTEP(t0 + 1, 1, false)
        BSTEP(t0 + 2, 2, false) BSTEP(t0 + 3, 3, false)
        BSTEP(t0 + 4, 4, false) BSTEP(t0 + 5, 5, false)
        BSTEP(t0 + 6, 6, false) BSTEP(t0 + 7, 7, false)
    }
#undef BSTEP
#undef WAITCH

    __syncwarp();

    // Backtrack. Reference forces dir=1 wherever attnmask==0, so for
    // t >= mellen the index stays pinned at textlen-1; inside the mask the
    // traced path never enters s >= textlen, so raw mk bits are correct.
    // De-chained in groups of 4 rows: index span <= 4 => 2 candidate bytes.
    if (L == 0) {
        int* gout = g_idx + b * CT;
        int idx = tl_b - 1;
        int t = CT - 1;
        for (; t >= ml_b; --t) gout[t] = idx;
        while (t >= 3) {
            int A  = idx >> 3;
            int Bq = ((idx >= 3) ? (idx - 3) : 0) >> 3;
            unsigned hi0 = sdir[t * 32 + A];
            unsigned hi1 = sdir[(t - 1) * 32 + A], lo1 = sdir[(t - 1) * 32 + Bq];
            unsigned hi2 = sdir[(t - 2) * 32 + A], lo2 = sdir[(t - 2) * 32 + Bq];
            unsigned hi3 = sdir[(t - 3) * 32 + A], lo3 = sdir[(t - 3) * 32 + Bq];
            gout[t] = idx;
            idx += (int)((hi0 >> (idx & 7)) & 1u) - 1;
            gout[t - 1] = idx;
            unsigned wd = ((idx >> 3) == A) ? hi1 : lo1;
            idx += (int)((wd >> (idx & 7)) & 1u) - 1;
            gout[t - 2] = idx;
            wd = ((idx >> 3) == A) ? hi2 : lo2;
            idx += (int)((wd >> (idx & 7)) & 1u) - 1;
            gout[t - 3] = idx;
            wd = ((idx >> 3) == A) ? hi3 : lo3;
            idx += (int)((wd >> (idx & 7)) & 1u) - 1;
            t -= 4;
        }
        for (; t >= 0; --t) {
            gout[t] = idx;
            idx += (int)((sdir[t * 32 + (idx >> 3)] >> (idx & 7)) & 1u) - 1;
        }
    }
}

// ---------------------------------------------------------------------------
// Kernel C: write residual [B,T,N] then attn [B,T,S] into d_out (float4).
// Also re-zeroes g_flag for the NEXT launch (stream-ordered after all flag
// use; flags are zero-initialized at module load for the first call).
// ---------------------------------------------------------------------------
__global__ __launch_bounds__(256)
void kernelC(const float* __restrict__ latent, const float* __restrict__ mean,
             const int* __restrict__ mellen, float* __restrict__ out)
{
    if (blockIdx.x == 0 && threadIdx.x < CB * 16)
        g_flag[threadIdx.x] = 0;

    const int RES4 = CB * CT * CN / 4;           // 655360
    const int TOT4 = RES4 + CB * CT * CS / 4;    // 2752512
    int i = blockIdx.x * blockDim.x + threadIdx.x;
    if (i >= TOT4) return;
    float4* out4 = (float4*)out;

    if (i < RES4) {
        int f  = i << 2;
        int bt = f / CN;
        int n  = f - bt * CN;
        int b  = bt >> 10;
        int t  = bt & (CT - 1);
        float4 r = ((const float4*)latent)[i];
        if (t < __ldg(&mellen[b])) {
            int sidx = g_idx[bt];
            float4 mv = *(const float4*)(mean + ((size_t)(b * CS + sidx)) * CN + n);
            r.x -= mv.x; r.y -= mv.y; r.z -= mv.z; r.w -= mv.w;
        }
        out4[i] = r;
    } else {
        int f  = (i - RES4) << 2;
        int bt = f >> 8;                 // / CS
        int s0 = f & (CS - 1);
        int b  = bt >> 10;
        int t  = bt & (CT - 1);
        float4 v = make_float4(0.f, 0.f, 0.f, 0.f);
        if (t < __ldg(&mellen[b])) {
            int sidx = g_idx[bt];        // always < textlen[b] => textmask == 1
            v.x = (sidx == s0)     ? 1.f : 0.f;
            v.y = (sidx == s0 + 1) ? 1.f : 0.f;
            v.z = (sidx == s0 + 2) ? 1.f : 0.f;
            v.w = (sidx == s0 + 3) ? 1.f : 0.f;
        }
        out4[i] = v;
    }
}

extern "C" void kernel_launch(void* const* d_in, const int* in_sizes, int n_in,
                              void* d_out, int out_size)
{
    const float* latent  = (const float*)d_in[0];   // [32,1024,80]
    const float* mean    = (const float*)d_in[1];   // [32,256,80]
    const int*   textlen = (const int*)d_in[2];     // [32]
    const int*   mellen  = (const int*)d_in[3];     // [32]
    float* out = (float*)d_out;                     // residual (B*T*N) ++ attn (B*T*S)

    const size_t shA = (size_t)(CN * 129 + CN * 65 + 128 + 64) * sizeof(float);
    cudaFuncSetAttribute(kernelAB, cudaFuncAttributeMaxDynamicSharedMemorySize, (int)shA);

    kernelAB<<<32 + CB * 32, 256, shA>>>(latent, mean, textlen, mellen);

    const int TOT4 = (CB * CT * CN + CB * CT * CS) / 4;
    kernelC<<<(TOT4 + 255) / 256, 256>>>(latent, mean, mellen, out);
}